// round 16
// baseline (speedup 1.0000x reference)
#include <cuda_runtime.h>
#include <cuda_bf16.h>
#include <math.h>
#include <stdint.h>

// ---------------- scratch (static __device__, no allocs) ----------------
__device__ unsigned int g_adj[512];          // adjacency bitmask (idempotent OR)
__device__ float g_P[128 * 512];
__device__ float g_Q[128 * 512];
__device__ float g_h1[128 * 512];
__device__ float g_h2[128 * 512];
__device__ float g_v0[512];
__device__ int   g_ticket;
__device__ __nv_bfloat16 g_w2t_hi[2][512 * 512];   // W2^T split: [n][k]
__device__ __nv_bfloat16 g_w2t_lo[2][512 * 512];

// ---------------- shared P/Q body (8d x 64h, 4-way k-split) ----------------
static __device__ void pq_body(const float* __restrict__ xin,
                               const float* __restrict__ W1,
                               const float* __restrict__ b1,
                               int C, int bx, int by,
                               float* xs, float* sred) {
    int dy = by * 8;
    int t = threadIdx.x;
    int hl = t & 63, kh = t >> 6;
    int h = bx * 64 + hl;
    for (int i = t; i < 8 * C; i += 256) xs[i] = xin[dy * C + i];
    __syncthreads();
    float p[8], q[8];
    #pragma unroll
    for (int j = 0; j < 8; j++) { p[j] = 0.f; q[j] = 0.f; }
    int k0 = kh * (C >> 2), k1 = k0 + (C >> 2);
    #pragma unroll 4
    for (int k = k0; k < k1; k++) {
        float wt = W1[k * 512 + h];
        float wb = W1[(C + k) * 512 + h];
        float df = wt - wb;
        #pragma unroll
        for (int j = 0; j < 8; j++) {
            float xv = xs[j * C + k];
            p[j] = fmaf(xv, df, p[j]);
            q[j] = fmaf(xv, wb, q[j]);
        }
    }
    if (kh > 0) {
        int base = (kh - 1) * 1024 + hl;
        #pragma unroll
        for (int j = 0; j < 8; j++) {
            sred[base + (2 * j) * 64]     = p[j];
            sred[base + (2 * j + 1) * 64] = q[j];
        }
    }
    __syncthreads();
    if (kh == 0) {
        float bb = b1[h];
        #pragma unroll
        for (int j = 0; j < 8; j++) {
            int off = (2 * j) * 64 + hl;
            float pp = p[j] + sred[off] + sred[1024 + off] + sred[2048 + off];
            off += 64;
            float qq = q[j] + sred[off] + sred[1024 + off] + sred[2048 + off];
            g_P[(dy + j) * 512 + h] = pp + bb;
            g_Q[(dy + j) * 512 + h] = qq;
        }
    }
}

// ---------------- fused front: prep_w2 + build_adj + pq(layer1) ------------
__global__ void front_kernel(const float* __restrict__ W2a,
                             const float* __restrict__ W2b,
                             const int* __restrict__ ei, int E,
                             const float* __restrict__ x,
                             const float* __restrict__ W1,
                             const float* __restrict__ b1) {
    __shared__ float smf[7168];   // 28 KB, aliased per role
    int bid = blockIdx.x;
    int t = threadIdx.x;

    if (bid < 512) {
        int layer = bid >> 8, idx = bid & 255;
        int nt = (idx & 15) * 32, kt = (idx >> 4) * 32;
        if (bid == 0) { g_v0[t] = 0.f; g_v0[t + 256] = 0.f; }
        const float* W2 = layer ? W2b : W2a;
        float (*ts)[33] = (float(*)[33])smf;
        int tx = t & 31, ty = t >> 5;
        #pragma unroll
        for (int j = 0; j < 4; j++)
            ts[ty + j * 8][tx] = W2[(kt + ty + j * 8) * 512 + nt + tx];
        __syncthreads();
        __nv_bfloat16* ph = g_w2t_hi[layer];
        __nv_bfloat16* pl = g_w2t_lo[layer];
        #pragma unroll
        for (int j = 0; j < 4; j++) {
            int n = nt + ty + j * 8;
            float v = ts[tx][ty + j * 8];
            __nv_bfloat16 h = __float2bfloat16(v);
            ph[n * 512 + kt + tx] = h;
            pl[n * 512 + kt + tx] = __float2bfloat16(v - __bfloat162float(h));
        }
    } else if (bid < 640) {
        unsigned int* s_adj = (unsigned int*)smf;
        for (int i = t; i < 512; i += 256) s_adj[i] = 0u;
        __syncthreads();
        int b = bid - 512;
        int stride = 128 * 256;
        for (int e = b * 256 + t; e < E; e += stride) {
            int s = ei[e];
            int d = ei[E + e];
            atomicOr(&s_adj[(d << 2) + (s >> 5)], 1u << (s & 31));
        }
        __syncthreads();
        for (int i = t; i < 512; i += 256) {
            unsigned int w = s_adj[i];
            if (w) atomicOr(&g_adj[i], w);
        }
    } else {
        int pb = bid - 640;
        pq_body(x, W1, b1, 256, pb & 7, pb >> 3, smf, smf + 4096);
    }
}

// ---------------- pq layer 2 ----------------
__global__ void pq_kernel(const float* __restrict__ W1,
                          const float* __restrict__ b1) {
    __shared__ float smf[7168];
    pq_body(g_h1, W1, b1, 512, blockIdx.x, blockIdx.y, smf, smf + 4096);
}

// ---------------- mma helpers ----------------
static __device__ __forceinline__ void mma16816(float* c, const uint32_t* a,
                                                uint32_t b0, uint32_t b1) {
    asm("mma.sync.aligned.m16n8k16.row.col.f32.bf16.bf16.f32 "
        "{%0,%1,%2,%3}, {%4,%5,%6,%7}, {%8,%9}, {%0,%1,%2,%3};"
        : "+f"(c[0]), "+f"(c[1]), "+f"(c[2]), "+f"(c[3])
        : "r"(a[0]), "r"(a[1]), "r"(a[2]), "r"(a[3]), "r"(b0), "r"(b1));
}
static __device__ __forceinline__ void ldm_x4(uint32_t* r, uint32_t addr) {
    asm volatile("ldmatrix.sync.aligned.m8n8.x4.shared.b16 {%0,%1,%2,%3}, [%4];"
                 : "=r"(r[0]), "=r"(r[1]), "=r"(r[2]), "=r"(r[3]) : "r"(addr));
}
static __device__ __forceinline__ uint32_t bf16x2_pack(float hi, float lo) {
    uint32_t r;
    asm("cvt.rn.bf16x2.f32 %0, %1, %2;" : "=r"(r) : "f"(hi), "f"(lo));
    return r;
}
static __device__ __forceinline__ uint32_t smem_u32(const void* p) {
    uint32_t a;
    asm("{ .reg .u64 t; cvta.to.shared.u64 t, %1; cvt.u32.u64 %0, t; }" : "=r"(a) : "l"(p));
    return a;
}
static __device__ __forceinline__ void cp16(uint32_t dst, const void* src) {
    asm volatile("cp.async.cg.shared.global [%0], [%1], 16;" :: "r"(dst), "l"(src) : "memory");
}

// ---------------- tensor-core pair-GEMM + masked segment-max ----------------
// grid (128 d, 4 n-quarters) = 512 CTAs, 256 thr = 8 warps (4m x 2n), 2 CTAs/SM.
// R16: when doDense, each CTA folds its h2 tile into the dense split-K partial
// (256 KB coalesced linW read, hidden under other CTAs' MMA), and the last CTA
// (ticket) runs lin1+out+softmax in-kernel.
#define KW 20
#define OFF_PS   0
#define OFF_ADJ  2048
#define OFF_A    2176
#define OFF_B    (OFF_A + 40960)                // 43136
#define GM_SMEM  (OFF_B + 40960)                // 84096

__global__ __launch_bounds__(256, 2) void gemm_mma_kernel(
        int layer, const float* __restrict__ b2, int outSel, int doDense,
        const float* __restrict__ linW, const float* __restrict__ lin_b,
        const float* __restrict__ lin1W, const float* __restrict__ lin1b,
        const float* __restrict__ outW, const float* __restrict__ outb,
        float* __restrict__ out) {
    extern __shared__ char smem[];
    float* Ps = (float*)(smem + OFF_PS);
    unsigned* adjw = (unsigned*)(smem + OFF_ADJ);
    uint32_t sb_A = smem_u32(smem) + OFF_A;
    uint32_t sb_B = smem_u32(smem) + OFF_B;

    int t = threadIdx.x, d = blockIdx.x;
    int nh = blockIdx.y;
    int wid = t >> 5, lane = t & 31;
    int g = lane >> 2, tq = lane & 3;
    int wm = (wid & 3) * 32;
    int wn = (wid >> 2) * 64;

    int lr = lane & 7, lm8 = (lane >> 3) & 1, ls16 = lane >> 4;
    uint32_t aRowOff = (uint32_t)(wm + lr + lm8 * 8) * 80u + (uint32_t)ls16 * 16u;
    uint32_t bRowOff = (uint32_t)(wn + ls16 * 8 + lr) * 80u + (uint32_t)lm8 * 16u;

    Ps[t]       = g_P[d * 512 + t];
    Ps[t + 256] = g_P[d * 512 + t + 256];
    if (t < 4) adjw[t] = g_adj[d * 4 + t];
    __syncthreads();

    unsigned am = adjw[wid & 3];
    bool ok[4];
    ok[0] = (am >> (g)) & 1u;
    ok[1] = (am >> (g + 8)) & 1u;
    ok[2] = (am >> (g + 16)) & 1u;
    ok[3] = (am >> (g + 24)) & 1u;

    int sA = t >> 1, hA = t & 1;
    int rB = t >> 1, segB = t & 1;

    const char* WHrow = (const char*)g_w2t_hi[layer] + (size_t)(nh * 128 + rB) * 1024;
    const char* WLrow = (const char*)g_w2t_lo[layer] + (size_t)(nh * 128 + rB) * 1024;
    const float4* Qrow = (const float4*)(g_Q + sA * 512 + hA * 16);
    float* outp = outSel ? g_h2 : g_h1;

    float c[2][8][4];
    #pragma unroll
    for (int mf = 0; mf < 2; mf++)
        #pragma unroll
        for (int nf = 0; nf < 8; nf++)
            #pragma unroll
            for (int i = 0; i < 4; i++) c[mf][nf][i] = 0.f;

    // ---- prologue: B tile 0 + A tile 0 into buf 0
    {
        uint32_t dh = sb_B + rB * 80 + segB * 32;
        cp16(dh, WHrow + segB * 32);
        cp16(dh + 16, WHrow + segB * 32 + 16);
        cp16(dh + 10240, WLrow + segB * 32);
        cp16(dh + 10256, WLrow + segB * 32 + 16);
        asm volatile("cp.async.commit_group;" ::: "memory");
    }
    {
        uint32_t* AH = (uint32_t*)(smem + OFF_A);
        uint32_t* AL = AH + 2560;
        #pragma unroll
        for (int j = 0; j < 4; j++) {
            float4 q = Qrow[j];
            int kb = hA * 16 + j * 4;
            float a0 = fmaxf(Ps[kb + 0] + q.x, 0.f);
            float a1 = fmaxf(Ps[kb + 1] + q.y, 0.f);
            float a2 = fmaxf(Ps[kb + 2] + q.z, 0.f);
            float a3 = fmaxf(Ps[kb + 3] + q.w, 0.f);
            uint32_t h01 = bf16x2_pack(a1, a0);
            uint32_t h23 = bf16x2_pack(a3, a2);
            float f0 = __uint_as_float(h01 << 16);
            float f1 = __uint_as_float(h01 & 0xffff0000u);
            float f2 = __uint_as_float(h23 << 16);
            float f3 = __uint_as_float(h23 & 0xffff0000u);
            int col = sA * KW + hA * 8 + j * 2;
            AH[col]     = h01;
            AH[col + 1] = h23;
            AL[col]     = bf16x2_pack(a1 - f1, a0 - f0);
            AL[col + 1] = bf16x2_pack(a3 - f3, a2 - f2);
        }
    }

    for (int it = 0; it < 16; it++) {
        int buf = it & 1, nbuf = buf ^ 1;

        asm volatile("cp.async.wait_group 0;" ::: "memory");
        __syncthreads();

        float4 s0, s1, s2, s3;
        if (it < 15) {
            uint32_t dh = sb_B + nbuf * 20480 + rB * 80 + segB * 32;
            const char* sh = WHrow + (it + 1) * 64 + segB * 32;
            const char* sl = WLrow + (it + 1) * 64 + segB * 32;
            cp16(dh, sh);           cp16(dh + 16, sh + 16);
            cp16(dh + 10240, sl);   cp16(dh + 10256, sl + 16);
            asm volatile("cp.async.commit_group;" ::: "memory");
            const float4* qp = Qrow + (it + 1) * 8;
            s0 = qp[0]; s1 = qp[1]; s2 = qp[2]; s3 = qp[3];
        }

        uint32_t baseAH = sb_A + buf * 20480 + aRowOff;
        uint32_t baseAL = baseAH + 10240;
        uint32_t baseBH = sb_B + buf * 20480 + bRowOff;
        uint32_t baseBL = baseBH + 10240;

        #pragma unroll
        for (int kf = 0; kf < 2; kf++) {
            uint32_t aH[2][4], aL[2][4];
            #pragma unroll
            for (int mf = 0; mf < 2; mf++) {
                ldm_x4(aH[mf], baseAH + mf * 1280 + kf * 32);
                ldm_x4(aL[mf], baseAL + mf * 1280 + kf * 32);
            }
            #pragma unroll
            for (int p = 0; p < 4; p++) {
                uint32_t bh[4], bl[4];
                ldm_x4(bh, baseBH + p * 1280 + kf * 32);
                ldm_x4(bl, baseBL + p * 1280 + kf * 32);
                #pragma unroll
                for (int sub = 0; sub < 2; sub++) {
                    int nf = 2 * p + sub;
                    #pragma unroll
                    for (int mf = 0; mf < 2; mf++) {
                        mma16816(c[mf][nf], aH[mf], bh[2 * sub], bh[2 * sub + 1]);
                        mma16816(c[mf][nf], aH[mf], bl[2 * sub], bl[2 * sub + 1]);
                        mma16816(c[mf][nf], aL[mf], bh[2 * sub], bh[2 * sub + 1]);
                    }
                }
            }
        }

        if (it < 15) {
            uint32_t* AH = (uint32_t*)(smem + OFF_A + nbuf * 20480);
            uint32_t* AL = AH + 2560;
            int k1 = (it + 1) * 32;
            float4 qs[4] = {s0, s1, s2, s3};
            #pragma unroll
            for (int j = 0; j < 4; j++) {
                float4 q = qs[j];
                int kb = k1 + hA * 16 + j * 4;
                float a0 = fmaxf(Ps[kb + 0] + q.x, 0.f);
                float a1 = fmaxf(Ps[kb + 1] + q.y, 0.f);
                float a2 = fmaxf(Ps[kb + 2] + q.z, 0.f);
                float a3 = fmaxf(Ps[kb + 3] + q.w, 0.f);
                uint32_t h01 = bf16x2_pack(a1, a0);
                uint32_t h23 = bf16x2_pack(a3, a2);
                float f0 = __uint_as_float(h01 << 16);
                float f1 = __uint_as_float(h01 & 0xffff0000u);
                float f2 = __uint_as_float(h23 << 16);
                float f3 = __uint_as_float(h23 & 0xffff0000u);
                int col = sA * KW + hA * 8 + j * 2;
                AH[col]     = h01;
                AH[col + 1] = h23;
                AL[col]     = bf16x2_pack(a1 - f1, a0 - f0);
                AL[col + 1] = bf16x2_pack(a3 - f3, a2 - f2);
            }
        }
    }

    // ---- epilogue: masked segment-max over s
    __syncthreads();
    float* red = (float*)(smem + OFF_A);
    #pragma unroll
    for (int nf = 0; nf < 8; nf++) {
        float v0 = -INFINITY, v1 = -INFINITY;
        if (ok[0]) { v0 = fmaxf(v0, c[0][nf][0]); v1 = fmaxf(v1, c[0][nf][1]); }
        if (ok[1]) { v0 = fmaxf(v0, c[0][nf][2]); v1 = fmaxf(v1, c[0][nf][3]); }
        if (ok[2]) { v0 = fmaxf(v0, c[1][nf][0]); v1 = fmaxf(v1, c[1][nf][1]); }
        if (ok[3]) { v0 = fmaxf(v0, c[1][nf][2]); v1 = fmaxf(v1, c[1][nf][3]); }
        #pragma unroll
        for (int off = 4; off < 32; off <<= 1) {
            v0 = fmaxf(v0, __shfl_xor_sync(0xffffffffu, v0, off));
            v1 = fmaxf(v1, __shfl_xor_sync(0xffffffffu, v1, off));
        }
        if (g == 0) {
            int col = wn + nf * 8 + 2 * tq;
            red[(wid & 3) * 128 + col]     = v0;
            red[(wid & 3) * 128 + col + 1] = v1;
        }
    }
    __syncthreads();
    float* vsd = (float*)(smem + OFF_B);   // h2 tile for dense partial
    if (t < 128) {
        float m = fmaxf(fmaxf(red[t], red[128 + t]),
                        fmaxf(red[256 + t], red[384 + t]));
        float hv = fmaxf(m + b2[nh * 128 + t], 0.f);
        outp[d * 512 + nh * 128 + t] = hv;
        vsd[t] = hv;
    }
    if (!doDense) return;
    __syncthreads();

    // ---- fused dense split-K partial: g_v0 += vsd @ linW[tile rows]
    {
        const float* Wd = linW + (size_t)(d * 512 + nh * 128) * 512;
        float a0 = 0.f, a1 = 0.f, a2 = 0.f, a3 = 0.f;
        #pragma unroll 4
        for (int k = 0; k < 128; k += 2) {
            float x0 = vsd[k], x1 = vsd[k + 1];
            const float* w0 = Wd + (size_t)k * 512;
            a0 = fmaf(x0, w0[t], a0);
            a1 = fmaf(x0, w0[t + 256], a1);
            a2 = fmaf(x1, w0[512 + t], a2);
            a3 = fmaf(x1, w0[512 + t + 256], a3);
        }
        atomicAdd(&g_v0[t], a0 + a2);
        atomicAdd(&g_v0[t + 256], a1 + a3);
    }

    __threadfence();
    __shared__ int isLast;
    if (t == 0) isLast = (atomicAdd(&g_ticket, 1) == 511);
    __syncthreads();
    if (!isLast) return;
    __threadfence();

    // ---- head: lin1 + out + relu + softmax (last CTA only)
    float* v0s = (float*)(smem + OFF_A);
    float* v1s = v0s + 512;
    float* lg  = v1s + 256;
    float* es  = lg + 128;
    v0s[t]       = fmaxf(*((volatile float*)&g_v0[t]) + lin_b[t], 0.f);
    v0s[t + 256] = fmaxf(*((volatile float*)&g_v0[t + 256]) + lin_b[t + 256], 0.f);
    __syncthreads();
    {
        float a = lin1b[t];
        #pragma unroll 8
        for (int k = 0; k < 512; k++) a = fmaf(v0s[k], lin1W[k * 256 + t], a);
        v1s[t] = fmaxf(a, 0.f);
    }
    __syncthreads();
    if (t < 128) {
        float a2 = outb[t];
        #pragma unroll 8
        for (int k = 0; k < 256; k++) a2 = fmaf(v1s[k], outW[k * 128 + t], a2);
        lg[t] = fmaxf(a2, 0.f);
    }
    __syncthreads();
    if (t < 128) {
        float mx = -INFINITY;
        for (int i = 0; i < 128; i++) mx = fmaxf(mx, lg[i]);
        es[t] = expf(lg[t] - mx);
    }
    __syncthreads();
    if (t < 128) {
        float sm = 0.f;
        for (int i = 0; i < 128; i++) sm += es[i];
        out[t] = es[t] / sm;
    }
    if (t == 0) g_ticket = 0;   // reset for next replay
}

// ---------------- launch ----------------
extern "C" void kernel_launch(void* const* d_in, const int* in_sizes, int n_in,
                              void* d_out, int out_size) {
    const float* x     = (const float*)d_in[0];
    const int*   ei    = (const int*)d_in[1];
    const float* c1W1  = (const float*)d_in[2];
    const float* c1b1  = (const float*)d_in[3];
    const float* c1W2  = (const float*)d_in[4];
    const float* c1b2  = (const float*)d_in[5];
    const float* c2W1  = (const float*)d_in[6];
    const float* c2b1  = (const float*)d_in[7];
    const float* c2W2  = (const float*)d_in[8];
    const float* c2b2  = (const float*)d_in[9];
    const float* linW  = (const float*)d_in[10];
    const float* linb  = (const float*)d_in[11];
    const float* lin1W = (const float*)d_in[12];
    const float* lin1b = (const float*)d_in[13];
    const float* outW  = (const float*)d_in[14];
    const float* outb  = (const float*)d_in[15];
    float* out = (float*)d_out;
    int E = in_sizes[1] / 2;

    cudaFuncSetAttribute(gemm_mma_kernel, cudaFuncAttributeMaxDynamicSharedMemorySize, GM_SMEM);

    front_kernel<<<768, 256>>>(c1W2, c2W2, ei, E, x, c1W1, c1b1);
    gemm_mma_kernel<<<dim3(128, 4), 256, GM_SMEM>>>(0, c1b2, 0, 0,
        nullptr, nullptr, nullptr, nullptr, nullptr, nullptr, nullptr);

    pq_kernel<<<dim3(8, 16), 256>>>(c2W1, c2b1);
    gemm_mma_kernel<<<dim3(128, 4), 256, GM_SMEM>>>(1, c2b2, 1, 1,
        linW, linb, lin1W, lin1b, outW, outb, out);
}

// round 17
// speedup vs baseline: 1.0200x; 1.0200x over previous
#include <cuda_runtime.h>
#include <cuda_bf16.h>
#include <math.h>
#include <stdint.h>

// ---------------- scratch (static __device__, no allocs) ----------------
__device__ unsigned int g_adj[512];          // adjacency bitmask (idempotent OR)
__device__ float g_P[128 * 512];
__device__ float g_Q[128 * 512];
__device__ float g_h1[128 * 512];
__device__ float g_h2[128 * 512];
__device__ float g_v0[512];
__device__ int   g_ticket;
__device__ __nv_bfloat16 g_w2t_hi[2][512 * 512];   // W2^T split: [n][k]
__device__ __nv_bfloat16 g_w2t_lo[2][512 * 512];

// ---------------- shared P/Q body (8d x 64h, 4-way k-split) ----------------
static __device__ void pq_body(const float* __restrict__ xin,
                               const float* __restrict__ W1,
                               const float* __restrict__ b1,
                               int C, int bx, int by,
                               float* xs, float* sred) {
    int dy = by * 8;
    int t = threadIdx.x;
    int hl = t & 63, kh = t >> 6;
    int h = bx * 64 + hl;
    for (int i = t; i < 8 * C; i += 256) xs[i] = xin[dy * C + i];
    __syncthreads();
    float p[8], q[8];
    #pragma unroll
    for (int j = 0; j < 8; j++) { p[j] = 0.f; q[j] = 0.f; }
    int k0 = kh * (C >> 2), k1 = k0 + (C >> 2);
    #pragma unroll 4
    for (int k = k0; k < k1; k++) {
        float wt = W1[k * 512 + h];
        float wb = W1[(C + k) * 512 + h];
        float df = wt - wb;
        #pragma unroll
        for (int j = 0; j < 8; j++) {
            float xv = xs[j * C + k];
            p[j] = fmaf(xv, df, p[j]);
            q[j] = fmaf(xv, wb, q[j]);
        }
    }
    if (kh > 0) {
        int base = (kh - 1) * 1024 + hl;
        #pragma unroll
        for (int j = 0; j < 8; j++) {
            sred[base + (2 * j) * 64]     = p[j];
            sred[base + (2 * j + 1) * 64] = q[j];
        }
    }
    __syncthreads();
    if (kh == 0) {
        float bb = b1[h];
        #pragma unroll
        for (int j = 0; j < 8; j++) {
            int off = (2 * j) * 64 + hl;
            float pp = p[j] + sred[off] + sred[1024 + off] + sred[2048 + off];
            off += 64;
            float qq = q[j] + sred[off] + sred[1024 + off] + sred[2048 + off];
            g_P[(dy + j) * 512 + h] = pp + bb;
            g_Q[(dy + j) * 512 + h] = qq;
        }
    }
}

// ---------------- fused front: prep_w2 + build_adj + pq(layer1) ------------
__global__ void front_kernel(const float* __restrict__ W2a,
                             const float* __restrict__ W2b,
                             const int* __restrict__ ei, int E,
                             const float* __restrict__ x,
                             const float* __restrict__ W1,
                             const float* __restrict__ b1) {
    __shared__ float smf[7168];   // 28 KB, aliased per role
    int bid = blockIdx.x;
    int t = threadIdx.x;

    if (bid < 512) {
        int layer = bid >> 8, idx = bid & 255;
        int nt = (idx & 15) * 32, kt = (idx >> 4) * 32;
        if (bid == 0) { g_v0[t] = 0.f; g_v0[t + 256] = 0.f; }
        const float* W2 = layer ? W2b : W2a;
        float (*ts)[33] = (float(*)[33])smf;
        int tx = t & 31, ty = t >> 5;
        #pragma unroll
        for (int j = 0; j < 4; j++)
            ts[ty + j * 8][tx] = W2[(kt + ty + j * 8) * 512 + nt + tx];
        __syncthreads();
        __nv_bfloat16* ph = g_w2t_hi[layer];
        __nv_bfloat16* pl = g_w2t_lo[layer];
        #pragma unroll
        for (int j = 0; j < 4; j++) {
            int n = nt + ty + j * 8;
            float v = ts[tx][ty + j * 8];
            __nv_bfloat16 h = __float2bfloat16(v);
            ph[n * 512 + kt + tx] = h;
            pl[n * 512 + kt + tx] = __float2bfloat16(v - __bfloat162float(h));
        }
    } else if (bid < 640) {
        unsigned int* s_adj = (unsigned int*)smf;
        for (int i = t; i < 512; i += 256) s_adj[i] = 0u;
        __syncthreads();
        int b = bid - 512;
        int stride = 128 * 256;
        for (int e = b * 256 + t; e < E; e += stride) {
            int s = ei[e];
            int d = ei[E + e];
            atomicOr(&s_adj[(d << 2) + (s >> 5)], 1u << (s & 31));
        }
        __syncthreads();
        for (int i = t; i < 512; i += 256) {
            unsigned int w = s_adj[i];
            if (w) atomicOr(&g_adj[i], w);
        }
    } else {
        int pb = bid - 640;
        pq_body(x, W1, b1, 256, pb & 7, pb >> 3, smf, smf + 4096);
    }
}

// ---------------- pq layer 2 ----------------
__global__ void pq_kernel(const float* __restrict__ W1,
                          const float* __restrict__ b1) {
    __shared__ float smf[7168];
    pq_body(g_h1, W1, b1, 512, blockIdx.x, blockIdx.y, smf, smf + 4096);
}

// ---------------- mma helpers ----------------
static __device__ __forceinline__ void mma16816(float* c, const uint32_t* a,
                                                uint32_t b0, uint32_t b1) {
    asm("mma.sync.aligned.m16n8k16.row.col.f32.bf16.bf16.f32 "
        "{%0,%1,%2,%3}, {%4,%5,%6,%7}, {%8,%9}, {%0,%1,%2,%3};"
        : "+f"(c[0]), "+f"(c[1]), "+f"(c[2]), "+f"(c[3])
        : "r"(a[0]), "r"(a[1]), "r"(a[2]), "r"(a[3]), "r"(b0), "r"(b1));
}
static __device__ __forceinline__ void ldm_x4(uint32_t* r, uint32_t addr) {
    asm volatile("ldmatrix.sync.aligned.m8n8.x4.shared.b16 {%0,%1,%2,%3}, [%4];"
                 : "=r"(r[0]), "=r"(r[1]), "=r"(r[2]), "=r"(r[3]) : "r"(addr));
}
static __device__ __forceinline__ uint32_t bf16x2_pack(float hi, float lo) {
    uint32_t r;
    asm("cvt.rn.bf16x2.f32 %0, %1, %2;" : "=r"(r) : "f"(hi), "f"(lo));
    return r;
}
static __device__ __forceinline__ uint32_t smem_u32(const void* p) {
    uint32_t a;
    asm("{ .reg .u64 t; cvta.to.shared.u64 t, %1; cvt.u32.u64 %0, t; }" : "=r"(a) : "l"(p));
    return a;
}
static __device__ __forceinline__ void cp16(uint32_t dst, const void* src) {
    asm volatile("cp.async.cg.shared.global [%0], [%1], 16;" :: "r"(dst), "l"(src) : "memory");
}

// ---------------- tensor-core pair-GEMM + masked segment-max ----------------
// grid (128 d, 4 n-quarters) = 512 CTAs, 256 thr = 8 warps (4m x 2n), 2 CTAs/SM.
// R17: fused dense partial rewritten as float4-vectorized 2-way k-split
// (64 coalesced LDG.128 per thread) so the 134 MB linW stream runs near BW.
#define KW 20
#define OFF_PS   0
#define OFF_ADJ  2048
#define OFF_A    2176
#define OFF_B    (OFF_A + 40960)                // 43136
#define GM_SMEM  (OFF_B + 40960)                // 84096

__global__ __launch_bounds__(256, 2) void gemm_mma_kernel(
        int layer, const float* __restrict__ b2, int outSel, int doDense,
        const float* __restrict__ linW, const float* __restrict__ lin_b,
        const float* __restrict__ lin1W, const float* __restrict__ lin1b,
        const float* __restrict__ outW, const float* __restrict__ outb,
        float* __restrict__ out) {
    extern __shared__ char smem[];
    float* Ps = (float*)(smem + OFF_PS);
    unsigned* adjw = (unsigned*)(smem + OFF_ADJ);
    uint32_t sb_A = smem_u32(smem) + OFF_A;
    uint32_t sb_B = smem_u32(smem) + OFF_B;

    int t = threadIdx.x, d = blockIdx.x;
    int nh = blockIdx.y;
    int wid = t >> 5, lane = t & 31;
    int g = lane >> 2, tq = lane & 3;
    int wm = (wid & 3) * 32;
    int wn = (wid >> 2) * 64;

    int lr = lane & 7, lm8 = (lane >> 3) & 1, ls16 = lane >> 4;
    uint32_t aRowOff = (uint32_t)(wm + lr + lm8 * 8) * 80u + (uint32_t)ls16 * 16u;
    uint32_t bRowOff = (uint32_t)(wn + ls16 * 8 + lr) * 80u + (uint32_t)lm8 * 16u;

    Ps[t]       = g_P[d * 512 + t];
    Ps[t + 256] = g_P[d * 512 + t + 256];
    if (t < 4) adjw[t] = g_adj[d * 4 + t];
    __syncthreads();

    unsigned am = adjw[wid & 3];
    bool ok[4];
    ok[0] = (am >> (g)) & 1u;
    ok[1] = (am >> (g + 8)) & 1u;
    ok[2] = (am >> (g + 16)) & 1u;
    ok[3] = (am >> (g + 24)) & 1u;

    int sA = t >> 1, hA = t & 1;
    int rB = t >> 1, segB = t & 1;

    const char* WHrow = (const char*)g_w2t_hi[layer] + (size_t)(nh * 128 + rB) * 1024;
    const char* WLrow = (const char*)g_w2t_lo[layer] + (size_t)(nh * 128 + rB) * 1024;
    const float4* Qrow = (const float4*)(g_Q + sA * 512 + hA * 16);
    float* outp = outSel ? g_h2 : g_h1;

    float c[2][8][4];
    #pragma unroll
    for (int mf = 0; mf < 2; mf++)
        #pragma unroll
        for (int nf = 0; nf < 8; nf++)
            #pragma unroll
            for (int i = 0; i < 4; i++) c[mf][nf][i] = 0.f;

    // ---- prologue: B tile 0 + A tile 0 into buf 0
    {
        uint32_t dh = sb_B + rB * 80 + segB * 32;
        cp16(dh, WHrow + segB * 32);
        cp16(dh + 16, WHrow + segB * 32 + 16);
        cp16(dh + 10240, WLrow + segB * 32);
        cp16(dh + 10256, WLrow + segB * 32 + 16);
        asm volatile("cp.async.commit_group;" ::: "memory");
    }
    {
        uint32_t* AH = (uint32_t*)(smem + OFF_A);
        uint32_t* AL = AH + 2560;
        #pragma unroll
        for (int j = 0; j < 4; j++) {
            float4 q = Qrow[j];
            int kb = hA * 16 + j * 4;
            float a0 = fmaxf(Ps[kb + 0] + q.x, 0.f);
            float a1 = fmaxf(Ps[kb + 1] + q.y, 0.f);
            float a2 = fmaxf(Ps[kb + 2] + q.z, 0.f);
            float a3 = fmaxf(Ps[kb + 3] + q.w, 0.f);
            uint32_t h01 = bf16x2_pack(a1, a0);
            uint32_t h23 = bf16x2_pack(a3, a2);
            float f0 = __uint_as_float(h01 << 16);
            float f1 = __uint_as_float(h01 & 0xffff0000u);
            float f2 = __uint_as_float(h23 << 16);
            float f3 = __uint_as_float(h23 & 0xffff0000u);
            int col = sA * KW + hA * 8 + j * 2;
            AH[col]     = h01;
            AH[col + 1] = h23;
            AL[col]     = bf16x2_pack(a1 - f1, a0 - f0);
            AL[col + 1] = bf16x2_pack(a3 - f3, a2 - f2);
        }
    }

    for (int it = 0; it < 16; it++) {
        int buf = it & 1, nbuf = buf ^ 1;

        asm volatile("cp.async.wait_group 0;" ::: "memory");
        __syncthreads();

        float4 s0, s1, s2, s3;
        if (it < 15) {
            uint32_t dh = sb_B + nbuf * 20480 + rB * 80 + segB * 32;
            const char* sh = WHrow + (it + 1) * 64 + segB * 32;
            const char* sl = WLrow + (it + 1) * 64 + segB * 32;
            cp16(dh, sh);           cp16(dh + 16, sh + 16);
            cp16(dh + 10240, sl);   cp16(dh + 10256, sl + 16);
            asm volatile("cp.async.commit_group;" ::: "memory");
            const float4* qp = Qrow + (it + 1) * 8;
            s0 = qp[0]; s1 = qp[1]; s2 = qp[2]; s3 = qp[3];
        }

        uint32_t baseAH = sb_A + buf * 20480 + aRowOff;
        uint32_t baseAL = baseAH + 10240;
        uint32_t baseBH = sb_B + buf * 20480 + bRowOff;
        uint32_t baseBL = baseBH + 10240;

        #pragma unroll
        for (int kf = 0; kf < 2; kf++) {
            uint32_t aH[2][4], aL[2][4];
            #pragma unroll
            for (int mf = 0; mf < 2; mf++) {
                ldm_x4(aH[mf], baseAH + mf * 1280 + kf * 32);
                ldm_x4(aL[mf], baseAL + mf * 1280 + kf * 32);
            }
            #pragma unroll
            for (int p = 0; p < 4; p++) {
                uint32_t bh[4], bl[4];
                ldm_x4(bh, baseBH + p * 1280 + kf * 32);
                ldm_x4(bl, baseBL + p * 1280 + kf * 32);
                #pragma unroll
                for (int sub = 0; sub < 2; sub++) {
                    int nf = 2 * p + sub;
                    #pragma unroll
                    for (int mf = 0; mf < 2; mf++) {
                        mma16816(c[mf][nf], aH[mf], bh[2 * sub], bh[2 * sub + 1]);
                        mma16816(c[mf][nf], aH[mf], bl[2 * sub], bl[2 * sub + 1]);
                        mma16816(c[mf][nf], aL[mf], bh[2 * sub], bh[2 * sub + 1]);
                    }
                }
            }
        }

        if (it < 15) {
            uint32_t* AH = (uint32_t*)(smem + OFF_A + nbuf * 20480);
            uint32_t* AL = AH + 2560;
            int k1 = (it + 1) * 32;
            float4 qs[4] = {s0, s1, s2, s3};
            #pragma unroll
            for (int j = 0; j < 4; j++) {
                float4 q = qs[j];
                int kb = k1 + hA * 16 + j * 4;
                float a0 = fmaxf(Ps[kb + 0] + q.x, 0.f);
                float a1 = fmaxf(Ps[kb + 1] + q.y, 0.f);
                float a2 = fmaxf(Ps[kb + 2] + q.z, 0.f);
                float a3 = fmaxf(Ps[kb + 3] + q.w, 0.f);
                uint32_t h01 = bf16x2_pack(a1, a0);
                uint32_t h23 = bf16x2_pack(a3, a2);
                float f0 = __uint_as_float(h01 << 16);
                float f1 = __uint_as_float(h01 & 0xffff0000u);
                float f2 = __uint_as_float(h23 << 16);
                float f3 = __uint_as_float(h23 & 0xffff0000u);
                int col = sA * KW + hA * 8 + j * 2;
                AH[col]     = h01;
                AH[col + 1] = h23;
                AL[col]     = bf16x2_pack(a1 - f1, a0 - f0);
                AL[col + 1] = bf16x2_pack(a3 - f3, a2 - f2);
            }
        }
    }

    // ---- epilogue: masked segment-max over s
    __syncthreads();
    float* red = (float*)(smem + OFF_A);
    #pragma unroll
    for (int nf = 0; nf < 8; nf++) {
        float v0 = -INFINITY, v1 = -INFINITY;
        if (ok[0]) { v0 = fmaxf(v0, c[0][nf][0]); v1 = fmaxf(v1, c[0][nf][1]); }
        if (ok[1]) { v0 = fmaxf(v0, c[0][nf][2]); v1 = fmaxf(v1, c[0][nf][3]); }
        if (ok[2]) { v0 = fmaxf(v0, c[1][nf][0]); v1 = fmaxf(v1, c[1][nf][1]); }
        if (ok[3]) { v0 = fmaxf(v0, c[1][nf][2]); v1 = fmaxf(v1, c[1][nf][3]); }
        #pragma unroll
        for (int off = 4; off < 32; off <<= 1) {
            v0 = fmaxf(v0, __shfl_xor_sync(0xffffffffu, v0, off));
            v1 = fmaxf(v1, __shfl_xor_sync(0xffffffffu, v1, off));
        }
        if (g == 0) {
            int col = wn + nf * 8 + 2 * tq;
            red[(wid & 3) * 128 + col]     = v0;
            red[(wid & 3) * 128 + col + 1] = v1;
        }
    }
    __syncthreads();
    float* vsd = (float*)(smem + OFF_B);   // h2 tile for dense partial
    if (t < 128) {
        float m = fmaxf(fmaxf(red[t], red[128 + t]),
                        fmaxf(red[256 + t], red[384 + t]));
        float hv = fmaxf(m + b2[nh * 128 + t], 0.f);
        outp[d * 512 + nh * 128 + t] = hv;
        vsd[t] = hv;
    }
    if (!doDense) return;
    __syncthreads();

    // ---- fused dense split-K partial (float4 stream, 2-way k-split)
    // thread t: n-quad nq = t&127 (n = nq*4), k-half = t>>7 (64 rows each).
    {
        int nq = t & 127, half = t >> 7;
        const float4* Wd4 = (const float4*)(linW + (size_t)(d * 512 + nh * 128) * 512) + nq;
        const float* vk = vsd + half * 64;
        const float4* W = Wd4 + (size_t)(half * 64) * 128;
        float4 acc = make_float4(0.f, 0.f, 0.f, 0.f);
        #pragma unroll 8
        for (int k = 0; k < 64; k++) {
            float xv = vk[k];
            float4 w = W[(size_t)k * 128];
            acc.x = fmaf(xv, w.x, acc.x);
            acc.y = fmaf(xv, w.y, acc.y);
            acc.z = fmaf(xv, w.z, acc.z);
            acc.w = fmaf(xv, w.w, acc.w);
        }
        float4* dred = (float4*)(smem + OFF_A);   // 128 float4 = 2 KB
        if (half == 1) dred[nq] = acc;
        __syncthreads();
        if (half == 0) {
            float4 o = dred[nq];
            atomicAdd(&g_v0[nq * 4 + 0], acc.x + o.x);
            atomicAdd(&g_v0[nq * 4 + 1], acc.y + o.y);
            atomicAdd(&g_v0[nq * 4 + 2], acc.z + o.z);
            atomicAdd(&g_v0[nq * 4 + 3], acc.w + o.w);
        }
    }

    __threadfence();
    __shared__ int isLast;
    if (t == 0) isLast = (atomicAdd(&g_ticket, 1) == 511);
    __syncthreads();
    if (!isLast) return;
    __threadfence();

    // ---- head: lin1 + out + relu + softmax (last CTA only)
    float* v0s = (float*)(smem + OFF_A);
    float* v1s = v0s + 512;
    float* lg  = v1s + 256;
    float* es  = lg + 128;
    v0s[t]       = fmaxf(*((volatile float*)&g_v0[t]) + lin_b[t], 0.f);
    v0s[t + 256] = fmaxf(*((volatile float*)&g_v0[t + 256]) + lin_b[t + 256], 0.f);
    __syncthreads();
    {
        float a = lin1b[t];
        #pragma unroll 8
        for (int k = 0; k < 512; k++) a = fmaf(v0s[k], lin1W[k * 256 + t], a);
        v1s[t] = fmaxf(a, 0.f);
    }
    __syncthreads();
    if (t < 128) {
        float a2 = outb[t];
        #pragma unroll 8
        for (int k = 0; k < 256; k++) a2 = fmaf(v1s[k], outW[k * 128 + t], a2);
        lg[t] = fmaxf(a2, 0.f);
    }
    __syncthreads();
    if (t < 128) {
        float mx = -INFINITY;
        for (int i = 0; i < 128; i++) mx = fmaxf(mx, lg[i]);
        es[t] = expf(lg[t] - mx);
    }
    __syncthreads();
    if (t < 128) {
        float sm = 0.f;
        for (int i = 0; i < 128; i++) sm += es[i];
        out[t] = es[t] / sm;
    }
    if (t == 0) g_ticket = 0;   // reset for next replay
}

// ---------------- launch ----------------
extern "C" void kernel_launch(void* const* d_in, const int* in_sizes, int n_in,
                              void* d_out, int out_size) {
    const float* x     = (const float*)d_in[0];
    const int*   ei    = (const int*)d_in[1];
    const float* c1W1  = (const float*)d_in[2];
    const float* c1b1  = (const float*)d_in[3];
    const float* c1W2  = (const float*)d_in[4];
    const float* c1b2  = (const float*)d_in[5];
    const float* c2W1  = (const float*)d_in[6];
    const float* c2b1  = (const float*)d_in[7];
    const float* c2W2  = (const float*)d_in[8];
    const float* c2b2  = (const float*)d_in[9];
    const float* linW  = (const float*)d_in[10];
    const float* linb  = (const float*)d_in[11];
    const float* lin1W = (const float*)d_in[12];
    const float* lin1b = (const float*)d_in[13];
    const float* outW  = (const float*)d_in[14];
    const float* outb  = (const float*)d_in[15];
    float* out = (float*)d_out;
    int E = in_sizes[1] / 2;

    cudaFuncSetAttribute(gemm_mma_kernel, cudaFuncAttributeMaxDynamicSharedMemorySize, GM_SMEM);

    front_kernel<<<768, 256>>>(c1W2, c2W2, ei, E, x, c1W1, c1b1);
    gemm_mma_kernel<<<dim3(128, 4), 256, GM_SMEM>>>(0, c1b2, 0, 0,
        nullptr, nullptr, nullptr, nullptr, nullptr, nullptr, nullptr);

    pq_kernel<<<dim3(8, 16), 256>>>(c2W1, c2b1);
    gemm_mma_kernel<<<dim3(128, 4), 256, GM_SMEM>>>(1, c2b2, 1, 1,
        linW, linb, lin1W, lin1b, outW, outb, out);
}